// round 2
// baseline (speedup 1.0000x reference)
#include <cuda_runtime.h>
#include <cuda_bf16.h>

// ---------------------------------------------------------------------------
// GlobalAttention: out = FC( softmax(mask(Q Kt)) V ) with projections
//   Q = query @ Wq^T + bq
//   C = key   @ Wk^T + bk ; K = C[:, :1024], V = C[:, 1024:]
//   S = Q K^T (per batch), masked where key_mask[b,k] != 0  -> -inf
//   P = softmax rows; O = P V; out = O @ Wfc^T + bfc
// All fp32. Scratch in __device__ globals (no allocations).
// key_mask read as 32-bit words; nonzero bits == masked. This is correct for
// both int32(0/1) and float32(0.0/1.0) encodings of the jax bool.
// ---------------------------------------------------------------------------

#define B_  4
#define LQ_ 2048
#define LK_ 2048
#define D_  1024

__device__ float g_Q[(long long)B_ * LQ_ * D_];        // 32 MB
__device__ float g_C[(long long)B_ * LK_ * 2 * D_];    // 64 MB (K|V per row)
__device__ float g_S[(long long)B_ * LQ_ * LK_];       // 64 MB
__device__ float g_O[(long long)B_ * LQ_ * D_];        // 32 MB

#define BM 128
#define BN 128
#define BK 8
#define TM 8
#define TN 8

// Generic tiled GEMM: C = A * op(B) + bias, optional column mask -> -1e30
// TRANS_B: B is (N x K) row-major (compute A B^T). else B is (K x N) row-major.
template <bool TRANS_B, bool DO_MASK>
__global__ void __launch_bounds__(256, 2)
gemm_kernel(const float* __restrict__ A, const float* __restrict__ Bm,
            const float* __restrict__ bias, const unsigned int* __restrict__ mask,
            float* __restrict__ C,
            int K, int lda, int ldb, int ldc,
            long long sA, long long sB, long long sC, long long sMask)
{
    __shared__ float As[BK][BM];
    __shared__ float Bs[BK][BN];

    const int bz = blockIdx.z;
    A  += (long long)bz * sA;
    Bm += (long long)bz * sB;
    C  += (long long)bz * sC;
    const unsigned int* mrow = DO_MASK ? (mask + (long long)bz * sMask) : nullptr;

    const int tid = threadIdx.x;
    const int tx = tid & 15;       // 0..15 -> column group
    const int ty = tid >> 4;       // 0..15 -> row group
    const int row0 = blockIdx.y * BM;
    const int col0 = blockIdx.x * BN;

    float acc[TM][TN];
#pragma unroll
    for (int i = 0; i < TM; i++)
#pragma unroll
        for (int j = 0; j < TN; j++) acc[i][j] = 0.f;

    const int a_r  = tid >> 1;         // 0..127 row within tile
    const int a_k4 = (tid & 1) * 4;    // 0 or 4
    const int b_k  = tid >> 5;         // 0..7   (NN layout)
    const int b_n4 = (tid & 31) * 4;   // 0..124 (NN layout)

    for (int k0 = 0; k0 < K; k0 += BK) {
        // --- load A tile (transpose into As[k][m]) ---
        float4 av = *reinterpret_cast<const float4*>(
            &A[(long long)(row0 + a_r) * lda + k0 + a_k4]);
        As[a_k4 + 0][a_r] = av.x;
        As[a_k4 + 1][a_r] = av.y;
        As[a_k4 + 2][a_r] = av.z;
        As[a_k4 + 3][a_r] = av.w;

        // --- load B tile into Bs[k][n] ---
        if (TRANS_B) {
            float4 bv = *reinterpret_cast<const float4*>(
                &Bm[(long long)(col0 + a_r) * ldb + k0 + a_k4]);
            Bs[a_k4 + 0][a_r] = bv.x;
            Bs[a_k4 + 1][a_r] = bv.y;
            Bs[a_k4 + 2][a_r] = bv.z;
            Bs[a_k4 + 3][a_r] = bv.w;
        } else {
            float4 bv = *reinterpret_cast<const float4*>(
                &Bm[(long long)(k0 + b_k) * ldb + col0 + b_n4]);
            *reinterpret_cast<float4*>(&Bs[b_k][b_n4]) = bv;
        }
        __syncthreads();

#pragma unroll
        for (int kk = 0; kk < BK; kk++) {
            float a[TM], b[TN];
#pragma unroll
            for (int i = 0; i < TM; i++) a[i] = As[kk][ty * TM + i];
#pragma unroll
            for (int j = 0; j < TN; j++) b[j] = Bs[kk][tx * TN + j];
#pragma unroll
            for (int i = 0; i < TM; i++)
#pragma unroll
                for (int j = 0; j < TN; j++)
                    acc[i][j] = fmaf(a[i], b[j], acc[i][j]);
        }
        __syncthreads();
    }

    // --- epilogue ---
#pragma unroll
    for (int i = 0; i < TM; i++) {
        const int m = row0 + ty * TM + i;
        float* crow = &C[(long long)m * ldc];
#pragma unroll
        for (int j = 0; j < TN; j++) {
            const int n = col0 + tx * TN + j;
            float v = acc[i][j];
            if (bias) v += bias[n];
            if (DO_MASK) {
                if (mrow[n] != 0u) v = -1e30f;   // works for i32 1 and f32 1.0
            }
            crow[n] = v;
        }
    }
}

// Row softmax over 2048 columns, in place. One block per row.
__global__ void __launch_bounds__(256)
softmax_kernel(float* __restrict__ S)
{
    const int NCOLS = LK_;
    const int NT = 256;
    float* p = S + (long long)blockIdx.x * NCOLS;
    const int tid = threadIdx.x;

    __shared__ float red[NT / 32];
    __shared__ float bc;

    float m = -3.402823e38f;
    for (int j = tid; j < NCOLS; j += NT) m = fmaxf(m, p[j]);
#pragma unroll
    for (int o = 16; o; o >>= 1) m = fmaxf(m, __shfl_xor_sync(0xffffffffu, m, o));
    if ((tid & 31) == 0) red[tid >> 5] = m;
    __syncthreads();
    if (tid < 32) {
        float t = (tid < NT / 32) ? red[tid] : -3.402823e38f;
#pragma unroll
        for (int o = 4; o; o >>= 1) t = fmaxf(t, __shfl_xor_sync(0xffffffffu, t, o));
        if (tid == 0) bc = t;
    }
    __syncthreads();
    m = bc;

    float s = 0.f;
    for (int j = tid; j < NCOLS; j += NT) {
        float e = expf(p[j] - m);
        p[j] = e;
        s += e;
    }
#pragma unroll
    for (int o = 16; o; o >>= 1) s += __shfl_xor_sync(0xffffffffu, s, o);
    __syncthreads();
    if ((tid & 31) == 0) red[tid >> 5] = s;
    __syncthreads();
    if (tid < 32) {
        float t = (tid < NT / 32) ? red[tid] : 0.f;
#pragma unroll
        for (int o = 4; o; o >>= 1) t += __shfl_xor_sync(0xffffffffu, t, o);
        if (tid == 0) bc = t;
    }
    __syncthreads();
    const float inv = 1.f / bc;
    for (int j = tid; j < NCOLS; j += NT) p[j] *= inv;
}

extern "C" void kernel_launch(void* const* d_in, const int* in_sizes, int n_in,
                              void* d_out, int out_size)
{
    // Bind inputs by element count (robust to metadata ordering).
    // Sizes: query/key = 8388608 (x2, order: query then key)
    //        key_mask  = 8192
    //        Wq/Wfc    = 1048576 (x2, order: Wq then Wfc)
    //        bq/bfc    = 1024    (x2, order: bq then bfc)
    //        Wk        = 2097152, bk = 2048
    const float *query = nullptr, *key = nullptr;
    const unsigned int* key_mask = nullptr;
    const float *Wq = nullptr, *bq = nullptr, *Wk = nullptr, *bk = nullptr;
    const float *Wfc = nullptr, *bfc = nullptr;

    for (int i = 0; i < n_in; i++) {
        const int sz = in_sizes[i];
        const void* p = d_in[i];
        switch (sz) {
            case 8388608: if (!query) query = (const float*)p; else key = (const float*)p; break;
            case 8192:    key_mask = (const unsigned int*)p; break;
            case 1048576: if (!Wq) Wq = (const float*)p; else Wfc = (const float*)p; break;
            case 1024:    if (!bq) bq = (const float*)p; else bfc = (const float*)p; break;
            case 2097152: Wk = (const float*)p; break;
            case 2048:    bk = (const float*)p; break;
            default: break;
        }
    }

    float* out = (float*)d_out;

    float *Q, *C, *S, *O;
    cudaGetSymbolAddress((void**)&Q, g_Q);
    cudaGetSymbolAddress((void**)&C, g_C);
    cudaGetSymbolAddress((void**)&S, g_S);
    cudaGetSymbolAddress((void**)&O, g_O);

    const dim3 blk(256);

    // 1) Q = query @ Wq^T + bq    (M=8192, N=1024, K=1024)
    {
        dim3 grid(D_ / BN, (B_ * LQ_) / BM, 1);
        gemm_kernel<true, false><<<grid, blk>>>(
            query, Wq, bq, nullptr, Q,
            D_, D_, D_, D_, 0, 0, 0, 0);
    }

    // 2) C = key @ Wk^T + bk      (M=8192, N=2048, K=1024)
    {
        dim3 grid((2 * D_) / BN, (B_ * LK_) / BM, 1);
        gemm_kernel<true, false><<<grid, blk>>>(
            key, Wk, bk, nullptr, C,
            D_, D_, D_, 2 * D_, 0, 0, 0, 0);
    }

    // 3) S = Q K^T, masked        (per batch: M=2048, N=2048, K=1024)
    {
        dim3 grid(LK_ / BN, LQ_ / BM, B_);
        gemm_kernel<true, true><<<grid, blk>>>(
            Q, C, nullptr, key_mask, S,
            D_, D_, 2 * D_, LK_,
            (long long)LQ_ * D_,
            (long long)LK_ * 2 * D_,
            (long long)LQ_ * LK_,
            LK_);
    }

    // 4) P = softmax(S) rows
    softmax_kernel<<<B_ * LQ_, blk>>>(S);

    // 5) O = P V                  (per batch: M=2048, N=1024, K=2048, NN)
    {
        dim3 grid(D_ / BN, LQ_ / BM, B_);
        gemm_kernel<false, false><<<grid, blk>>>(
            S, C + D_, nullptr, nullptr, O,
            LK_, LK_, 2 * D_, D_,
            (long long)LQ_ * LK_,
            (long long)LK_ * 2 * D_,
            (long long)LQ_ * D_, 0);
    }

    // 6) out = O @ Wfc^T + bfc    (M=8192, N=1024, K=1024)
    {
        dim3 grid(D_ / BN, (B_ * LQ_) / BM, 1);
        gemm_kernel<true, false><<<grid, blk>>>(
            O, Wfc, bfc, nullptr, out,
            D_, D_, D_, D_, 0, 0, 0, 0);
    }
}

// round 4
// speedup vs baseline: 2.2337x; 2.2337x over previous
#include <cuda_runtime.h>
#include <cuda_bf16.h>
#include <cstdint>

// ===========================================================================
// GlobalAttention via mma.sync bf16 (sm_103 plain target; tcgen05 PTX is
// rejected by this harness's compute_103 virtual arch).
// fp32 emulated by 3xBF16 split: A*B ~= Ah*Bh + Ah*Bl + Al*Bh  (err ~2^-17)
//   G1: Q = query@Wq^T + bq          -> Qh/Ql
//   G2: C = key@Wk^T + bk            -> Kh/Kl (n<1024), Vt h/l transposed
//   G3: S = Q K^T (batched), mask    -> S fp32
//   softmax rows -> Ph/Pl
//   G4: O = P Vt^T (batched)         -> Oh/Ol
//   G5: out = O@Wfc^T + bfc          -> fp32
// All GEMMs: D[M,N] = A[M,K]*B[N,K]^T, K-major row-major both sides.
// ===========================================================================

#define B_  4
#define LQ_ 2048
#define LK_ 2048
#define D_  1024

__device__ float          g_S  [(long long)B_ * LQ_ * LK_];
__device__ __nv_bfloat16  g_qh [(long long)B_ * LQ_ * D_];
__device__ __nv_bfloat16  g_ql [(long long)B_ * LQ_ * D_];
__device__ __nv_bfloat16  g_kh [(long long)B_ * LK_ * D_];
__device__ __nv_bfloat16  g_kl [(long long)B_ * LK_ * D_];
__device__ __nv_bfloat16  g_wqh[(long long)D_ * D_];
__device__ __nv_bfloat16  g_wql[(long long)D_ * D_];
__device__ __nv_bfloat16  g_wkh[(long long)2 * D_ * D_];
__device__ __nv_bfloat16  g_wkl[(long long)2 * D_ * D_];
__device__ __nv_bfloat16  g_wfh[(long long)D_ * D_];
__device__ __nv_bfloat16  g_wfl[(long long)D_ * D_];
__device__ __nv_bfloat16  g_Qh [(long long)B_ * LQ_ * D_];
__device__ __nv_bfloat16  g_Ql [(long long)B_ * LQ_ * D_];
__device__ __nv_bfloat16  g_Kh [(long long)B_ * LK_ * D_];
__device__ __nv_bfloat16  g_Kl [(long long)B_ * LK_ * D_];
__device__ __nv_bfloat16  g_Vth[(long long)B_ * D_ * LK_];
__device__ __nv_bfloat16  g_Vtl[(long long)B_ * D_ * LK_];
__device__ __nv_bfloat16  g_Ph [(long long)B_ * LQ_ * LK_];
__device__ __nv_bfloat16  g_Pl [(long long)B_ * LQ_ * LK_];
__device__ __nv_bfloat16  g_Oh [(long long)B_ * LQ_ * D_];
__device__ __nv_bfloat16  g_Ol [(long long)B_ * LQ_ * D_];

// ---- helpers ----
__device__ __forceinline__ uint32_t smem_u32(const void* p) {
    uint32_t a;
    asm("{ .reg .u64 t; cvta.to.shared.u64 t, %1; cvt.u32.u64 %0, t; }" : "=r"(a) : "l"(p));
    return a;
}
__device__ __forceinline__ void cp16(uint32_t saddr, const void* gaddr) {
    asm volatile("cp.async.cg.shared.global [%0], [%1], 16;\n" :: "r"(saddr), "l"(gaddr));
}
#define CP_COMMIT() asm volatile("cp.async.commit_group;\n" ::: "memory")
#define CP_WAIT(n)  asm volatile("cp.async.wait_group %0;\n" :: "n"(n) : "memory")

__device__ __forceinline__ void ldsm4(uint32_t* r, uint32_t a) {
    asm volatile("ldmatrix.sync.aligned.m8n8.x4.shared.b16 {%0,%1,%2,%3}, [%4];"
                 : "=r"(r[0]), "=r"(r[1]), "=r"(r[2]), "=r"(r[3]) : "r"(a));
}
__device__ __forceinline__ void mma16816(float* d, const uint32_t* a,
                                         uint32_t b0, uint32_t b1) {
    asm volatile("mma.sync.aligned.m16n8k16.row.col.f32.bf16.bf16.f32 "
                 "{%0,%1,%2,%3}, {%4,%5,%6,%7}, {%8,%9}, {%0,%1,%2,%3};"
                 : "+f"(d[0]), "+f"(d[1]), "+f"(d[2]), "+f"(d[3])
                 : "r"(a[0]), "r"(a[1]), "r"(a[2]), "r"(a[3]), "r"(b0), "r"(b1));
}

// ---- GEMM config: CTA 128x128, k-chunk 32 bf16, 4-stage cp.async pipeline ----
#define RB 80                        // smem row stride (bytes); 5 mod 8 -> conflict-free ldsm
#define STG (128 * RB)               // 10240 B per operand tile
#define AOFF(s) ((s) * 2 * STG)
#define BOFF(s) (AOFF(s) + STG)
#define SMEM_BYTES (8 * STG)         // 81920

// EPI: 0 = bf16 hi/lo pair (+opt bias); 1 = like 0 for n<1024, transposed V pair for n>=1024;
//      2 = masked fp32; 3 = fp32 + bias
template <int EPI>
__global__ void __launch_bounds__(256, 2)
mma_gemm(const __nv_bfloat16* __restrict__ Ah, const __nv_bfloat16* __restrict__ Al,
         const __nv_bfloat16* __restrict__ Bh, const __nv_bfloat16* __restrict__ Bl,
         const float* __restrict__ bias, const unsigned int* __restrict__ mask,
         void* __restrict__ o0h, void* __restrict__ o0l,
         void* __restrict__ o1h, void* __restrict__ o1l,
         int K, int ldc, long long sA, long long sB, long long sO, long long sM)
{
    extern __shared__ char smem[];
    const uint32_t sb = smem_u32(smem);
    const int tid = threadIdx.x, lid = tid & 31, wid = tid >> 5;
    const int wm = wid & 3, wn = wid >> 2;
    const int bz = blockIdx.z;
    Ah += (long long)bz * sA;  Al += (long long)bz * sA;
    Bh += (long long)bz * sB;  Bl += (long long)bz * sB;
    const long long obase = (long long)bz * sO;
    const unsigned int* mrow = (EPI == 2) ? (mask + (long long)bz * sM) : nullptr;
    const int row0 = blockIdx.y * 128, col0 = blockIdx.x * 128;

    float d[2][8][4];
#pragma unroll
    for (int i = 0; i < 2; i++)
#pragma unroll
        for (int j = 0; j < 8; j++)
#pragma unroll
            for (int k = 0; k < 4; k++) d[i][j][k] = 0.f;

    const int NC = (K / 32) * 3;

    auto issue = [&](int c) {
        const int t = c % 3, kk = (c / 3) * 32;
        const __nv_bfloat16* Ap = (t == 2) ? Al : Ah;
        const __nv_bfloat16* Bp = (t == 1) ? Bl : Bh;
        const uint32_t ab = sb + AOFF(c & 3), bb = sb + BOFF(c & 3);
#pragma unroll
        for (int i = 0; i < 2; i++) {
            const int u = tid + i * 256;
            const int r = u >> 2, c16 = u & 3;
            cp16(ab + r * RB + c16 * 16, Ap + (long long)(row0 + r) * K + kk + c16 * 8);
            cp16(bb + r * RB + c16 * 16, Bp + (long long)(col0 + r) * K + kk + c16 * 8);
        }
        CP_COMMIT();
    };

    issue(0); issue(1); issue(2);

    for (int c = 0; c < NC; c++) {
        const int rem = NC - 1 - c;
        if (rem >= 2)      { CP_WAIT(2); }
        else if (rem == 1) { CP_WAIT(1); }
        else               { CP_WAIT(0); }
        __syncthreads();                 // data visible + prev chunk's compute done
        if (c + 3 < NC) issue(c + 3);    // overwrites stage (c-1)&3 — safe post-barrier

        const uint32_t ab = sb + AOFF(c & 3), bb = sb + BOFF(c & 3);
        const int rsel = lid & 15;
#pragma unroll
        for (int q = 0; q < 2; q++) {
            const int c16 = q * 2 + (lid >> 4);
            uint32_t a[2][4], b[4][4];
#pragma unroll
            for (int mi = 0; mi < 2; mi++)
                ldsm4(a[mi], ab + (wm * 32 + mi * 16 + rsel) * RB + c16 * 16);
#pragma unroll
            for (int nj = 0; nj < 4; nj++)
                ldsm4(b[nj], bb + (wn * 64 + nj * 16 + rsel) * RB + c16 * 16);
#pragma unroll
            for (int mi = 0; mi < 2; mi++)
#pragma unroll
                for (int nj = 0; nj < 4; nj++) {
                    mma16816(d[mi][nj * 2],     a[mi], b[nj][0], b[nj][2]);
                    mma16816(d[mi][nj * 2 + 1], a[mi], b[nj][1], b[nj][3]);
                }
        }
    }
    __syncthreads();   // before smem reuse in epilogue

    const int r0l = lid >> 2;
    const int c0l = (lid & 3) * 2;

    if (EPI == 1 && col0 >= D_) {
        // ---- transposed V epilogue: Vt[b][d][l] ----
        __nv_bfloat16* Th = (__nv_bfloat16*)(smem + wid * 8704);
        __nv_bfloat16* Tl = (__nv_bfloat16*)(smem + wid * 8704 + 4352);
#pragma unroll
        for (int mi = 0; mi < 2; mi++)
#pragma unroll
            for (int ni = 0; ni < 8; ni++) {
                const int gn = col0 + wn * 64 + ni * 8 + c0l;
                const float b0 = bias[gn], b1 = bias[gn + 1];
                const int dl0 = ni * 8 + c0l;
#pragma unroll
                for (int rr = 0; rr < 2; rr++) {
                    const int lloc = mi * 16 + r0l + rr * 8;
                    const float x0 = d[mi][ni][rr * 2] + b0;
                    const float x1 = d[mi][ni][rr * 2 + 1] + b1;
                    __nv_bfloat16 h0 = __float2bfloat16(x0);
                    __nv_bfloat16 h1 = __float2bfloat16(x1);
                    __nv_bfloat16 q0 = __float2bfloat16(x0 - __bfloat162float(h0));
                    __nv_bfloat16 q1 = __float2bfloat16(x1 - __bfloat162float(h1));
                    Th[dl0 * 34 + lloc] = h0;  Th[(dl0 + 1) * 34 + lloc] = h1;
                    Tl[dl0 * 34 + lloc] = q0;  Tl[(dl0 + 1) * 34 + lloc] = q1;
                }
            }
        __syncwarp();
        const int b = row0 >> 11;
        const int l0 = (row0 & 2047) + wm * 32;
#pragma unroll
        for (int k = 0; k < 2; k++) {
            const int dl = lid + k * 32;
            const long long dst =
                ((long long)b * D_ + (col0 - D_ + wn * 64 + dl)) * LK_ + l0;
            const uint32_t* srch = (const uint32_t*)(Th + dl * 34);
            const uint32_t* srcl = (const uint32_t*)(Tl + dl * 34);
            uint32_t* dsh = (uint32_t*)((__nv_bfloat16*)o1h + dst);
            uint32_t* dsl = (uint32_t*)((__nv_bfloat16*)o1l + dst);
#pragma unroll
            for (int j = 0; j < 16; j++) { dsh[j] = srch[j]; dsl[j] = srcl[j]; }
        }
    } else {
#pragma unroll
        for (int mi = 0; mi < 2; mi++)
#pragma unroll
            for (int ni = 0; ni < 8; ni++) {
                const int gn = col0 + wn * 64 + ni * 8 + c0l;
                float b0 = 0.f, b1 = 0.f;
                if (EPI != 2 && bias) { b0 = bias[gn]; b1 = bias[gn + 1]; }
                unsigned int mw0 = 0, mw1 = 0;
                if (EPI == 2) { mw0 = mrow[gn]; mw1 = mrow[gn + 1]; }
#pragma unroll
                for (int rr = 0; rr < 2; rr++) {
                    const long long gm = row0 + wm * 32 + mi * 16 + r0l + rr * 8;
                    const float x0 = d[mi][ni][rr * 2] + b0;
                    const float x1 = d[mi][ni][rr * 2 + 1] + b1;
                    const long long off = obase + gm * ldc + gn;
                    if (EPI == 2) {
                        float2 v;
                        v.x = mw0 ? -1e30f : x0;
                        v.y = mw1 ? -1e30f : x1;
                        *(float2*)((float*)o0h + off) = v;
                    } else if (EPI == 3) {
                        float2 v; v.x = x0; v.y = x1;
                        *(float2*)((float*)o0h + off) = v;
                    } else {
                        __nv_bfloat16 h0 = __float2bfloat16(x0);
                        __nv_bfloat16 h1 = __float2bfloat16(x1);
                        __nv_bfloat16 q0 = __float2bfloat16(x0 - __bfloat162float(h0));
                        __nv_bfloat16 q1 = __float2bfloat16(x1 - __bfloat162float(h1));
                        __nv_bfloat162 hp; hp.x = h0; hp.y = h1;
                        __nv_bfloat162 lp; lp.x = q0; lp.y = q1;
                        *(__nv_bfloat162*)((__nv_bfloat16*)o0h + off) = hp;
                        *(__nv_bfloat162*)((__nv_bfloat16*)o0l + off) = lp;
                    }
                }
            }
    }
}

// ---- fp32 -> bf16 hi/lo split ----
__global__ void __launch_bounds__(256)
split_kernel(const float* __restrict__ x, __nv_bfloat16* __restrict__ h,
             __nv_bfloat16* __restrict__ l, long long n4)
{
    long long i = (long long)blockIdx.x * blockDim.x + threadIdx.x;
    if (i >= n4) return;
    float4 v = ((const float4*)x)[i];
    float vv[4] = {v.x, v.y, v.z, v.w};
    __nv_bfloat16 hh[4], ll[4];
#pragma unroll
    for (int j = 0; j < 4; j++) {
        hh[j] = __float2bfloat16(vv[j]);
        ll[j] = __float2bfloat16(vv[j] - __bfloat162float(hh[j]));
    }
    ((uint2*)h)[i] = *(uint2*)hh;
    ((uint2*)l)[i] = *(uint2*)ll;
}

// ---- softmax: S row -> P hi/lo bf16 ----
__global__ void __launch_bounds__(256)
softmax_split(const float* __restrict__ S, __nv_bfloat16* __restrict__ Ph,
              __nv_bfloat16* __restrict__ Pl)
{
    const int tid = threadIdx.x;
    const long long row = blockIdx.x;
    const float* p = S + row * LK_;
    float4 a = ((const float4*)p)[tid * 2];
    float4 b = ((const float4*)p)[tid * 2 + 1];
    float r[8] = {a.x, a.y, a.z, a.w, b.x, b.y, b.z, b.w};

    __shared__ float red[8];
    __shared__ float bc;

    float m = r[0];
#pragma unroll
    for (int j = 1; j < 8; j++) m = fmaxf(m, r[j]);
#pragma unroll
    for (int o = 16; o; o >>= 1) m = fmaxf(m, __shfl_xor_sync(0xffffffffu, m, o));
    if ((tid & 31) == 0) red[tid >> 5] = m;
    __syncthreads();
    if (tid < 32) {
        float t = (tid < 8) ? red[tid] : -3.402823e38f;
#pragma unroll
        for (int o = 4; o; o >>= 1) t = fmaxf(t, __shfl_xor_sync(0xffffffffu, t, o));
        if (tid == 0) bc = t;
    }
    __syncthreads();
    m = bc;

    float s = 0.f;
#pragma unroll
    for (int j = 0; j < 8; j++) { r[j] = expf(r[j] - m); s += r[j]; }
#pragma unroll
    for (int o = 16; o; o >>= 1) s += __shfl_xor_sync(0xffffffffu, s, o);
    __syncthreads();
    if ((tid & 31) == 0) red[tid >> 5] = s;
    __syncthreads();
    if (tid < 32) {
        float t = (tid < 8) ? red[tid] : 0.f;
#pragma unroll
        for (int o = 4; o; o >>= 1) t += __shfl_xor_sync(0xffffffffu, t, o);
        if (tid == 0) bc = t;
    }
    __syncthreads();
    const float inv = 1.f / bc;

    __nv_bfloat16 hh[8], ll[8];
#pragma unroll
    for (int j = 0; j < 8; j++) {
        float v = r[j] * inv;
        hh[j] = __float2bfloat16(v);
        ll[j] = __float2bfloat16(v - __bfloat162float(hh[j]));
    }
    ((uint4*)(Ph + row * LK_))[tid] = *(uint4*)hh;
    ((uint4*)(Pl + row * LK_))[tid] = *(uint4*)ll;
}

// ---------------------------------------------------------------------------
extern "C" void kernel_launch(void* const* d_in, const int* in_sizes, int n_in,
                              void* d_out, int out_size)
{
    const float *query = nullptr, *key = nullptr;
    const unsigned int* key_mask = nullptr;
    const float *Wq = nullptr, *bq = nullptr, *Wk = nullptr, *bk = nullptr;
    const float *Wfc = nullptr, *bfc = nullptr;
    for (int i = 0; i < n_in; i++) {
        const int sz = in_sizes[i];
        const void* p = d_in[i];
        switch (sz) {
            case 8388608: if (!query) query = (const float*)p; else key = (const float*)p; break;
            case 8192:    key_mask = (const unsigned int*)p; break;
            case 1048576: if (!Wq) Wq = (const float*)p; else Wfc = (const float*)p; break;
            case 1024:    if (!bq) bq = (const float*)p; else bfc = (const float*)p; break;
            case 2097152: Wk = (const float*)p; break;
            case 2048:    bk = (const float*)p; break;
            default: break;
        }
    }
    float* out = (float*)d_out;

    float* S;           cudaGetSymbolAddress((void**)&S,   g_S);
    __nv_bfloat16 *qh, *ql, *kh, *kl, *wqh, *wql, *wkh, *wkl, *wfh, *wfl;
    __nv_bfloat16 *Qh, *Ql, *Kh, *Kl, *Vth, *Vtl, *Ph, *Pl, *Oh, *Ol;
    cudaGetSymbolAddress((void**)&qh,  g_qh);  cudaGetSymbolAddress((void**)&ql,  g_ql);
    cudaGetSymbolAddress((void**)&kh,  g_kh);  cudaGetSymbolAddress((void**)&kl,  g_kl);
    cudaGetSymbolAddress((void**)&wqh, g_wqh); cudaGetSymbolAddress((void**)&wql, g_wql);
    cudaGetSymbolAddress((void**)&wkh, g_wkh); cudaGetSymbolAddress((void**)&wkl, g_wkl);
    cudaGetSymbolAddress((void**)&wfh, g_wfh); cudaGetSymbolAddress((void**)&wfl, g_wfl);
    cudaGetSymbolAddress((void**)&Qh,  g_Qh);  cudaGetSymbolAddress((void**)&Ql,  g_Ql);
    cudaGetSymbolAddress((void**)&Kh,  g_Kh);  cudaGetSymbolAddress((void**)&Kl,  g_Kl);
    cudaGetSymbolAddress((void**)&Vth, g_Vth); cudaGetSymbolAddress((void**)&Vtl, g_Vtl);
    cudaGetSymbolAddress((void**)&Ph,  g_Ph);  cudaGetSymbolAddress((void**)&Pl,  g_Pl);
    cudaGetSymbolAddress((void**)&Oh,  g_Oh);  cudaGetSymbolAddress((void**)&Ol,  g_Ol);

    cudaFuncSetAttribute(mma_gemm<0>, cudaFuncAttributeMaxDynamicSharedMemorySize, SMEM_BYTES);
    cudaFuncSetAttribute(mma_gemm<1>, cudaFuncAttributeMaxDynamicSharedMemorySize, SMEM_BYTES);
    cudaFuncSetAttribute(mma_gemm<2>, cudaFuncAttributeMaxDynamicSharedMemorySize, SMEM_BYTES);
    cudaFuncSetAttribute(mma_gemm<3>, cudaFuncAttributeMaxDynamicSharedMemorySize, SMEM_BYTES);

    // ---- input splits ----
    {
        long long n4;
        n4 = (long long)B_ * LQ_ * D_ / 4;
        split_kernel<<<(unsigned)((n4 + 255) / 256), 256>>>(query, qh, ql, n4);
        split_kernel<<<(unsigned)((n4 + 255) / 256), 256>>>(key,   kh, kl, n4);
        n4 = (long long)D_ * D_ / 4;
        split_kernel<<<(unsigned)((n4 + 255) / 256), 256>>>(Wq,  wqh, wql, n4);
        split_kernel<<<(unsigned)((n4 + 255) / 256), 256>>>(Wfc, wfh, wfl, n4);
        n4 = (long long)2 * D_ * D_ / 4;
        split_kernel<<<(unsigned)((n4 + 255) / 256), 256>>>(Wk,  wkh, wkl, n4);
    }

    const dim3 blk(256);

    // G1: Q = query @ Wq^T + bq  -> Qh/Ql
    {
        dim3 grid(D_ / 128, (B_ * LQ_) / 128, 1);
        mma_gemm<0><<<grid, blk, SMEM_BYTES>>>(
            qh, ql, wqh, wql, bq, nullptr,
            Qh, Ql, nullptr, nullptr,
            D_, D_, 0, 0, 0, 0);
    }
    // G2: C = key @ Wk^T + bk -> Kh/Kl + Vth/Vtl (transposed)
    {
        dim3 grid((2 * D_) / 128, (B_ * LK_) / 128, 1);
        mma_gemm<1><<<grid, blk, SMEM_BYTES>>>(
            kh, kl, wkh, wkl, bk, nullptr,
            Kh, Kl, Vth, Vtl,
            D_, D_, 0, 0, 0, 0);
    }
    // G3: S = Q K^T (batched), masked -> S fp32
    {
        dim3 grid(LK_ / 128, LQ_ / 128, B_);
        mma_gemm<2><<<grid, blk, SMEM_BYTES>>>(
            Qh, Ql, Kh, Kl, nullptr, key_mask,
            S, nullptr, nullptr, nullptr,
            D_, LK_,
            (long long)LQ_ * D_, (long long)LK_ * D_,
            (long long)LQ_ * LK_, LK_);
    }
    // softmax -> Ph/Pl
    softmax_split<<<B_ * LQ_, 256>>>(S, Ph, Pl);
    // G4: O = P Vt^T (batched) -> Oh/Ol
    {
        dim3 grid(D_ / 128, LQ_ / 128, B_);
        mma_gemm<0><<<grid, blk, SMEM_BYTES>>>(
            Ph, Pl, Vth, Vtl, nullptr, nullptr,
            Oh, Ol, nullptr, nullptr,
            LK_, D_,
            (long long)LQ_ * LK_, (long long)D_ * LK_,
            (long long)LQ_ * D_, 0);
    }
    // G5: out = O @ Wfc^T + bfc -> fp32
    {
        dim3 grid(D_ / 128, (B_ * LQ_) / 128, 1);
        mma_gemm<3><<<grid, blk, SMEM_BYTES>>>(
            Oh, Ol, wfh, wfl, bfc, nullptr,
            out, nullptr, nullptr, nullptr,
            D_, D_, 0, 0, 0, 0);
    }
}